// round 7
// baseline (speedup 1.0000x reference)
#include <cuda_runtime.h>
#include <cstdint>

// ---------------------------------------------------------------------------
// TGN layer-graph sum embedding, fused per layer. Round 7 (third submit of the
// R5 pipeline kernel; R5/R6 benches died at GB300 container acquisition —
// broker infra, kernel never compiled/ran. Audit found no hang path: uniform
// barriers, every wait_group matched, chunk-lockstep orders all smem hazards).
// vs round 4 (L1 72.9%, fma 45.7%, cp.async serialized per chunk):
//  - double-buffered cp.async W pipeline (16-row chunks): wait covers the
//    chunk issued one full compute-chunk earlier -> latency hidden; ONE
//    barrier per chunk (was 2 + exposed wait)
//  - W1 chunk0 prefetched at kernel entry (hides under phase A)
//  - swizzle dropped; transposed-A pitch 72 (mod 32 = 8): conflict-free
//    lane-consecutive GEMM reads with immediate-offset LDS, zero inner-loop
//    ALU (R4 had alu pipe at 23.4% from XOR address math)
//  - smem 70KB -> still 3 CTAs/SM
// ---------------------------------------------------------------------------

#define DD   128
#define KK   16
#define DE   32
#define DT   32
#define D1   192
#define TB   64
#define PT   72            // transposed-A pitch (mod 32 == 8 -> conflict-free)
#define CH   16            // W chunk rows
#define NMAX 100000

typedef unsigned long long ull;

__device__ float g_buf[(size_t)NMAX * DD];

__device__ __forceinline__ ull dup2(float x) {
    ull r; asm("mov.b64 %0, {%1, %1};" : "=l"(r) : "f"(x)); return r;
}
__device__ __forceinline__ void ffma2(ull& d, ull a, ull b) {
    asm("fma.rn.f32x2 %0, %1, %2, %3;" : "=l"(d) : "l"(a), "l"(b), "l"(d));
}
__device__ __forceinline__ float2 unpk(ull v) {
    float2 r; asm("mov.b64 {%0, %1}, %2;" : "=f"(r.x), "=f"(r.y) : "l"(v)); return r;
}
__device__ __forceinline__ void cpa16(uint32_t dst, const void* src) {
    asm volatile("cp.async.cg.shared.global [%0], [%1], 16;" :: "r"(dst), "l"(src));
}
__device__ __forceinline__ void cp_commit() {
    asm volatile("cp.async.commit_group;");
}
__device__ __forceinline__ void cp_wait0() {
    asm volatile("cp.async.wait_group 0;");
}

__device__ __forceinline__ void issue_chunk(uint32_t wsa, int buf,
                                            const float* Wg, int chunk, int tid) {
    const float4* s = (const float4*)(Wg + (size_t)chunk * CH * DD);
    uint32_t d = wsa + (uint32_t)buf * (CH * DD * 4);
    cpa16(d + (uint32_t)tid * 16,         s + tid);
    cpa16(d + (uint32_t)(tid + 256) * 16, s + tid + 256);
    cp_commit();
}

// acc[2 nodes][8 col-pairs] += A(kRows x 64, pitch PT, transposed)^T @ W.
// W streamed in CH-row chunks, double-buffered via cp.async.
// If pre==true, chunk 0 was already issued by the caller.
// NO trailing barrier: caller must __syncthreads before overwriting AsT.
__device__ __forceinline__ void gemm_T(
    const float* __restrict__ AsT,
    const float* __restrict__ Wg,
    const float* __restrict__ Ws, uint32_t wsa,
    int nCh,
    ull acc[2][8], int lane, int cw, int tid, bool pre)
{
    if (!pre) issue_chunk(wsa, 0, Wg, 0, tid);
    for (int c = 0; c < nCh; c++) {
        cp_wait0();
        __syncthreads();          // chunk c visible; prior buf reads done
        if (c + 1 < nCh) issue_chunk(wsa, (c + 1) & 1, Wg, c + 1, tid);

        const float* ap = AsT + (size_t)c * CH * PT + lane;
        const float* wb = Ws + (c & 1) * (CH * DD) + cw;
        #pragma unroll
        for (int kk = 0; kk < CH; kk++) {
            float a0 = ap[kk * PT];
            float a1 = ap[kk * PT + 32];
            ull A0 = dup2(a0);
            ull A1 = dup2(a1);
            const ulonglong2* wp = (const ulonglong2*)(wb + kk * DD);
            ulonglong2 w0 = wp[0], w1 = wp[1], w2 = wp[2], w3 = wp[3];
            ffma2(acc[0][0], A0, w0.x); ffma2(acc[0][1], A0, w0.y);
            ffma2(acc[0][2], A0, w1.x); ffma2(acc[0][3], A0, w1.y);
            ffma2(acc[0][4], A0, w2.x); ffma2(acc[0][5], A0, w2.y);
            ffma2(acc[0][6], A0, w3.x); ffma2(acc[0][7], A0, w3.y);
            ffma2(acc[1][0], A1, w0.x); ffma2(acc[1][1], A1, w0.y);
            ffma2(acc[1][2], A1, w1.x); ffma2(acc[1][3], A1, w1.y);
            ffma2(acc[1][4], A1, w2.x); ffma2(acc[1][5], A1, w2.y);
            ffma2(acc[1][6], A1, w3.x); ffma2(acc[1][7], A1, w3.y);
        }
    }
}

extern "C" __global__ void __launch_bounds__(256, 3)
tgn_layer(const float* __restrict__ src,
          const float* __restrict__ e,
          const float* __restrict__ t,
          const float* __restrict__ W1g,
          const float* __restrict__ b1g,
          const float* __restrict__ W2g,
          const float* __restrict__ b2g,
          const void* __restrict__ idxRaw,
          int layer,
          float* __restrict__ dst,
          int N)
{
    extern __shared__ float sm[];
    float* aggT = sm;                 // [192][PT] transposed; rows 0..127 reused
    float* Ws   = aggT + D1 * PT;     // [2][CH*128] double buffer
    __shared__ int s_flag;

    const int tid  = threadIdx.x;
    const int lane = tid & 31;
    const int w    = tid >> 5;
    const int base = blockIdx.x * TB;
    const uint32_t wsa = (uint32_t)__cvta_generic_to_shared(Ws);

    // prefetch W1 chunk 0 under phase A
    issue_chunk(wsa, 0, W1g, 0, tid);

    // idx dtype detection (int64 values < 1e5 -> every odd 32-bit word == 0)
    if (tid == 0) s_flag = 0;
    __syncthreads();
    if (tid < 64) {
        int v = ((const int*)idxRaw)[2 * tid + 1];
        if (v != 0) atomicOr(&s_flag, 1);
    }
    __syncthreads();
    const int idx64 = (s_flag == 0);

    const long long* i64 = (const long long*)idxRaw + (size_t)layer * N * KK;
    const int*       i32 = (const int*)idxRaw       + (size_t)layer * N * KK;

    // ---------------- Phase A: aggregation -> transposed smem ---------------
    #pragma unroll 1
    for (int i = 0; i < 8; i++) {
        int ln = w * 8 + i;
        int n  = base + ln;
        if (n >= N) continue;
        float4 accA = {0.f,0.f,0.f,0.f}, accB = {0.f,0.f,0.f,0.f};
        float es = 0.f, ts = 0.f;

        #pragma unroll
        for (int jj = 0; jj < 4; jj++) {
            long long q0, q1, q2, q3;
            if (idx64) {
                const long long* p = i64 + (size_t)n * KK + jj * 4;
                q0 = p[0]; q1 = p[1]; q2 = p[2]; q3 = p[3];
            } else {
                int4 v = ((const int4*)(i32 + (size_t)n * KK))[jj];
                q0 = v.x; q1 = v.y; q2 = v.z; q3 = v.w;
            }
            float4 v0 = ((const float4*)(src + (size_t)q0 * DD))[lane];
            float4 v1 = ((const float4*)(src + (size_t)q1 * DD))[lane];
            float4 v2 = ((const float4*)(src + (size_t)q2 * DD))[lane];
            float4 v3 = ((const float4*)(src + (size_t)q3 * DD))[lane];
            accA.x += v0.x; accA.y += v0.y; accA.z += v0.z; accA.w += v0.w;
            accB.x += v1.x; accB.y += v1.y; accB.z += v1.z; accB.w += v1.w;
            accA.x += v2.x; accA.y += v2.y; accA.z += v2.z; accA.w += v2.w;
            accB.x += v3.x; accB.y += v3.y; accB.z += v3.z; accB.w += v3.w;
        }
        const float* ep = e + (size_t)n * (KK * DE);
        const float* tp = t + (size_t)n * (KK * DT);
        #pragma unroll
        for (int j = 0; j < KK; j++) {
            es += ep[j * DE + lane];
            ts += tp[j * DT + lane];
        }
        accA.x += accB.x; accA.y += accB.y; accA.z += accB.z; accA.w += accB.w;

        int r0 = 4 * lane;
        aggT[(r0 + 0) * PT + ln] = accA.x;
        aggT[(r0 + 1) * PT + ln] = accA.y;
        aggT[(r0 + 2) * PT + ln] = accA.z;
        aggT[(r0 + 3) * PT + ln] = accA.w;
        aggT[(DD + lane) * PT + ln]      = es;
        aggT[(DD + DE + lane) * PT + ln] = ts;
    }
    __syncthreads();

    // ---------------- Phase B: h = relu(agg @ W1 + b1) ----------------------
    const int cw = w * 16;
    ull acc[2][8];
    #pragma unroll
    for (int i = 0; i < 2; i++)
        #pragma unroll
        for (int j = 0; j < 8; j++) acc[i][j] = 0ull;

    gemm_T(aggT, W1g, Ws, wsa, D1 / CH, acc, lane, cw, tid, true);

    // h -> aggT rows [cw, cw+16). Safe without barrier: the final GEMM1 chunk
    // reads rows 176..191 only; rows 0..127 reads all precede the last
    // in-gemm barrier (chunk lockstep).
    #pragma unroll
    for (int j = 0; j < 8; j++) {
        float2 v0 = unpk(acc[0][j]);
        float2 v1 = unpk(acc[1][j]);
        int c0 = cw + 2 * j;
        float bb0 = b1g[c0], bb1 = b1g[c0 + 1];
        float* p0 = &aggT[c0 * PT + lane];
        float* p1 = &aggT[(c0 + 1) * PT + lane];
        p0[0]  = fmaxf(v0.x + bb0, 0.f);
        p1[0]  = fmaxf(v0.y + bb1, 0.f);
        p0[32] = fmaxf(v1.x + bb0, 0.f);
        p1[32] = fmaxf(v1.y + bb1, 0.f);
        acc[0][j] = 0ull; acc[1][j] = 0ull;
    }
    __syncthreads();   // all h visible before C1 reads

    // ---------------- Phase C1: acc += h @ W2[128:256] ----------------------
    gemm_T(aggT, W2g + DD * DD, Ws, wsa, DD / CH, acc, lane, cw, tid, false);
    __syncthreads();   // C1 reads of rows 0..127 done before reload overwrites

    // ---------------- reload own rows (L2-hot) over aggT rows 0..127 --------
    {
        const float4* cp4 = (const float4*)(src + (size_t)base * DD);
        #pragma unroll
        for (int i = 0; i < 8; i++) {
            int f  = tid + 256 * i;      // 0..2047
            int n  = f >> 5;             // node 0..63
            int k4 = f & 31;
            if (base + n < N) {
                float4 v = cp4[f];
                int r = 4 * k4;
                aggT[(r + 0) * PT + n] = v.x;
                aggT[(r + 1) * PT + n] = v.y;
                aggT[(r + 2) * PT + n] = v.z;
                aggT[(r + 3) * PT + n] = v.w;
            }
        }
    }
    // no barrier needed: gemm_T's internal chunk-0 barrier (wait+sync) orders
    // these STS before any C2 LDS (BAR.SYNC drains pending STS).

    // ---------------- Phase C2: acc += cur @ W2[0:128] ----------------------
    gemm_T(aggT, W2g, Ws, wsa, DD / CH, acc, lane, cw, tid, false);

    #pragma unroll
    for (int half = 0; half < 2; half++) {
        int n = base + lane + half * 32;
        if (n < N) {
            float o[16];
            #pragma unroll
            for (int j = 0; j < 8; j++) {
                float2 v = unpk(acc[half][j]);
                o[2*j]     = v.x + b2g[cw + 2*j];
                o[2*j + 1] = v.y + b2g[cw + 2*j + 1];
            }
            float* dp = dst + (size_t)n * DD + cw;
            #pragma unroll
            for (int q = 0; q < 4; q++)
                *(float4*)(dp + 4 * q) = *(float4*)&o[4 * q];
        }
    }
}

extern "C" void kernel_launch(void* const* d_in, const int* in_sizes, int n_in,
                              void* d_out, int out_size)
{
    const float* features = (const float*)d_in[0];
    const float* edge     = (const float*)d_in[1];
    const float* timef    = (const float*)d_in[2];
    const float* W1       = (const float*)d_in[3];
    const float* b1       = (const float*)d_in[4];
    const float* W2       = (const float*)d_in[5];
    const float* b2       = (const float*)d_in[6];
    const void*  idx      = d_in[7];
    float*       out      = (float*)d_out;

    const int N = in_sizes[0] / DD;

    const size_t smem = (size_t)(D1 * PT + 2 * CH * DD) * sizeof(float); // 71680 B
    cudaFuncSetAttribute(tgn_layer, cudaFuncAttributeMaxDynamicSharedMemorySize, (int)smem);

    void* gptr = nullptr;
    cudaGetSymbolAddress(&gptr, g_buf);
    float* gbuf = (float*)gptr;

    const int blocks = (N + TB - 1) / TB;
    const size_t eoff = (size_t)N * KK * DE;
    const size_t toff = (size_t)N * KK * DT;

    tgn_layer<<<blocks, 256, smem>>>(features, edge, timef,
                                     W1, b1, W2, b2, idx, 0, gbuf, N);
    tgn_layer<<<blocks, 256, smem>>>(gbuf, edge + eoff, timef + toff,
                                     W1 + D1 * DD, b1 + DD,
                                     W2 + 2 * DD * DD, b2 + DD,
                                     idx, 1, out, N);
}

// round 10
// speedup vs baseline: 1.1655x; 1.1655x over previous
#include <cuda_runtime.h>
#include <cstdint>

// ---------------------------------------------------------------------------
// TGN layer-graph sum embedding, fused per layer. Round 10 (3rd submit of the
// PT=65 kernel; R8/R9 benches died at GB300 container acquisition — broker
// infra. R5/R6-fail -> R7-pass on identical source proves failures are
// uncorrelated with kernel content. No hang path: uniform barriers, every
// wait_group matched, chunk-lockstep orders all smem hazards.)
// R7 post-mortem: pitch-72 transposed STORES had inter-lane stride 4*72=288
// == 0 mod 32 -> 32-way bank conflicts on every phase-A store and the phase-C
// reload (L1 83.4%, regression to 443us/layer). GEMM reads were fine.
// Fix: PT = 65. Reads stay stride-1 conflict-free; transposed stores/reload
// become stride 260 == 4 mod 32 -> 4-way (8 banks). smem 66.3KB, 3 CTAs/SM.
// Everything else identical to R7 (double-buffered cp.async W pipeline,
// 16-row chunks, W1 chunk0 prefetched under phase A, FFMA2 inner loop).
// ---------------------------------------------------------------------------

#define DD   128
#define KK   16
#define DE   32
#define DT   32
#define D1   192
#define TB   64
#define PT   65            // transposed-A pitch: reads stride-1; stores 4-way
#define CH   16            // W chunk rows
#define NMAX 100000

typedef unsigned long long ull;

__device__ float g_buf[(size_t)NMAX * DD];

__device__ __forceinline__ ull dup2(float x) {
    ull r; asm("mov.b64 %0, {%1, %1};" : "=l"(r) : "f"(x)); return r;
}
__device__ __forceinline__ void ffma2(ull& d, ull a, ull b) {
    asm("fma.rn.f32x2 %0, %1, %2, %3;" : "=l"(d) : "l"(a), "l"(b), "l"(d));
}
__device__ __forceinline__ float2 unpk(ull v) {
    float2 r; asm("mov.b64 {%0, %1}, %2;" : "=f"(r.x), "=f"(r.y) : "l"(v)); return r;
}
__device__ __forceinline__ void cpa16(uint32_t dst, const void* src) {
    asm volatile("cp.async.cg.shared.global [%0], [%1], 16;" :: "r"(dst), "l"(src));
}
__device__ __forceinline__ void cp_commit() {
    asm volatile("cp.async.commit_group;");
}
__device__ __forceinline__ void cp_wait0() {
    asm volatile("cp.async.wait_group 0;");
}

__device__ __forceinline__ void issue_chunk(uint32_t wsa, int buf,
                                            const float* Wg, int chunk, int tid) {
    const float4* s = (const float4*)(Wg + (size_t)chunk * CH * DD);
    uint32_t d = wsa + (uint32_t)buf * (CH * DD * 4);
    cpa16(d + (uint32_t)tid * 16,         s + tid);
    cpa16(d + (uint32_t)(tid + 256) * 16, s + tid + 256);
    cp_commit();
}

// acc[2 nodes][8 col-pairs] += A(kRows x 64, pitch PT, transposed)^T @ W.
// W streamed in CH-row chunks, double-buffered via cp.async.
// If pre==true, chunk 0 was already issued by the caller.
// NO trailing barrier: caller must __syncthreads before overwriting AsT.
__device__ __forceinline__ void gemm_T(
    const float* __restrict__ AsT,
    const float* __restrict__ Wg,
    const float* __restrict__ Ws, uint32_t wsa,
    int nCh,
    ull acc[2][8], int lane, int cw, int tid, bool pre)
{
    if (!pre) issue_chunk(wsa, 0, Wg, 0, tid);
    for (int c = 0; c < nCh; c++) {
        cp_wait0();
        __syncthreads();          // chunk c visible; prior buf reads done
        if (c + 1 < nCh) issue_chunk(wsa, (c + 1) & 1, Wg, c + 1, tid);

        const float* ap = AsT + (size_t)c * CH * PT + lane;
        const float* wb = Ws + (c & 1) * (CH * DD) + cw;
        #pragma unroll
        for (int kk = 0; kk < CH; kk++) {
            float a0 = ap[kk * PT];
            float a1 = ap[kk * PT + 32];
            ull A0 = dup2(a0);
            ull A1 = dup2(a1);
            const ulonglong2* wp = (const ulonglong2*)(wb + kk * DD);
            ulonglong2 w0 = wp[0], w1 = wp[1], w2 = wp[2], w3 = wp[3];
            ffma2(acc[0][0], A0, w0.x); ffma2(acc[0][1], A0, w0.y);
            ffma2(acc[0][2], A0, w1.x); ffma2(acc[0][3], A0, w1.y);
            ffma2(acc[0][4], A0, w2.x); ffma2(acc[0][5], A0, w2.y);
            ffma2(acc[0][6], A0, w3.x); ffma2(acc[0][7], A0, w3.y);
            ffma2(acc[1][0], A1, w0.x); ffma2(acc[1][1], A1, w0.y);
            ffma2(acc[1][2], A1, w1.x); ffma2(acc[1][3], A1, w1.y);
            ffma2(acc[1][4], A1, w2.x); ffma2(acc[1][5], A1, w2.y);
            ffma2(acc[1][6], A1, w3.x); ffma2(acc[1][7], A1, w3.y);
        }
    }
}

extern "C" __global__ void __launch_bounds__(256, 3)
tgn_layer(const float* __restrict__ src,
          const float* __restrict__ e,
          const float* __restrict__ t,
          const float* __restrict__ W1g,
          const float* __restrict__ b1g,
          const float* __restrict__ W2g,
          const float* __restrict__ b2g,
          const void* __restrict__ idxRaw,
          int layer,
          float* __restrict__ dst,
          int N)
{
    extern __shared__ float sm[];
    float* aggT = sm;                 // [192][PT] transposed; rows 0..127 reused
    float* Ws   = aggT + D1 * PT;     // [2][CH*128] double buffer
    __shared__ int s_flag;

    const int tid  = threadIdx.x;
    const int lane = tid & 31;
    const int w    = tid >> 5;
    const int base = blockIdx.x * TB;
    const uint32_t wsa = (uint32_t)__cvta_generic_to_shared(Ws);

    // prefetch W1 chunk 0 under phase A
    issue_chunk(wsa, 0, W1g, 0, tid);

    // idx dtype detection (int64 values < 1e5 -> every odd 32-bit word == 0)
    if (tid == 0) s_flag = 0;
    __syncthreads();
    if (tid < 64) {
        int v = ((const int*)idxRaw)[2 * tid + 1];
        if (v != 0) atomicOr(&s_flag, 1);
    }
    __syncthreads();
    const int idx64 = (s_flag == 0);

    const long long* i64 = (const long long*)idxRaw + (size_t)layer * N * KK;
    const int*       i32 = (const int*)idxRaw       + (size_t)layer * N * KK;

    // ---------------- Phase A: aggregation -> transposed smem ---------------
    #pragma unroll 1
    for (int i = 0; i < 8; i++) {
        int ln = w * 8 + i;
        int n  = base + ln;
        if (n >= N) continue;
        float4 accA = {0.f,0.f,0.f,0.f}, accB = {0.f,0.f,0.f,0.f};
        float es = 0.f, ts = 0.f;

        #pragma unroll
        for (int jj = 0; jj < 4; jj++) {
            long long q0, q1, q2, q3;
            if (idx64) {
                const long long* p = i64 + (size_t)n * KK + jj * 4;
                q0 = p[0]; q1 = p[1]; q2 = p[2]; q3 = p[3];
            } else {
                int4 v = ((const int4*)(i32 + (size_t)n * KK))[jj];
                q0 = v.x; q1 = v.y; q2 = v.z; q3 = v.w;
            }
            float4 v0 = ((const float4*)(src + (size_t)q0 * DD))[lane];
            float4 v1 = ((const float4*)(src + (size_t)q1 * DD))[lane];
            float4 v2 = ((const float4*)(src + (size_t)q2 * DD))[lane];
            float4 v3 = ((const float4*)(src + (size_t)q3 * DD))[lane];
            accA.x += v0.x; accA.y += v0.y; accA.z += v0.z; accA.w += v0.w;
            accB.x += v1.x; accB.y += v1.y; accB.z += v1.z; accB.w += v1.w;
            accA.x += v2.x; accA.y += v2.y; accA.z += v2.z; accA.w += v2.w;
            accB.x += v3.x; accB.y += v3.y; accB.z += v3.z; accB.w += v3.w;
        }
        const float* ep = e + (size_t)n * (KK * DE);
        const float* tp = t + (size_t)n * (KK * DT);
        #pragma unroll
        for (int j = 0; j < KK; j++) {
            es += ep[j * DE + lane];
            ts += tp[j * DT + lane];
        }
        accA.x += accB.x; accA.y += accB.y; accA.z += accB.z; accA.w += accB.w;

        int r0 = 4 * lane;
        aggT[(r0 + 0) * PT + ln] = accA.x;
        aggT[(r0 + 1) * PT + ln] = accA.y;
        aggT[(r0 + 2) * PT + ln] = accA.z;
        aggT[(r0 + 3) * PT + ln] = accA.w;
        aggT[(DD + lane) * PT + ln]      = es;
        aggT[(DD + DE + lane) * PT + ln] = ts;
    }
    __syncthreads();

    // ---------------- Phase B: h = relu(agg @ W1 + b1) ----------------------
    const int cw = w * 16;
    ull acc[2][8];
    #pragma unroll
    for (int i = 0; i < 2; i++)
        #pragma unroll
        for (int j = 0; j < 8; j++) acc[i][j] = 0ull;

    gemm_T(aggT, W1g, Ws, wsa, D1 / CH, acc, lane, cw, tid, true);

    // h -> aggT rows [cw, cw+16). Safe without barrier: the final GEMM1 chunk
    // reads rows 176..191 only; rows 0..127 reads all precede the last
    // in-gemm barrier (chunk lockstep).
    #pragma unroll
    for (int j = 0; j < 8; j++) {
        float2 v0 = unpk(acc[0][j]);
        float2 v1 = unpk(acc[1][j]);
        int c0 = cw + 2 * j;
        float bb0 = b1g[c0], bb1 = b1g[c0 + 1];
        float* p0 = &aggT[c0 * PT + lane];
        float* p1 = &aggT[(c0 + 1) * PT + lane];
        p0[0]  = fmaxf(v0.x + bb0, 0.f);
        p1[0]  = fmaxf(v0.y + bb1, 0.f);
        p0[32] = fmaxf(v1.x + bb0, 0.f);
        p1[32] = fmaxf(v1.y + bb1, 0.f);
        acc[0][j] = 0ull; acc[1][j] = 0ull;
    }
    __syncthreads();   // all h visible before C1 reads

    // ---------------- Phase C1: acc += h @ W2[128:256] ----------------------
    gemm_T(aggT, W2g + DD * DD, Ws, wsa, DD / CH, acc, lane, cw, tid, false);
    __syncthreads();   // C1 reads of rows 0..127 done before reload overwrites

    // ---------------- reload own rows (L2-hot) over aggT rows 0..127 --------
    {
        const float4* cp4 = (const float4*)(src + (size_t)base * DD);
        #pragma unroll
        for (int i = 0; i < 8; i++) {
            int f  = tid + 256 * i;      // 0..2047
            int n  = f >> 5;             // node 0..63
            int k4 = f & 31;
            if (base + n < N) {
                float4 v = cp4[f];
                int r = 4 * k4;
                aggT[(r + 0) * PT + n] = v.x;
                aggT[(r + 1) * PT + n] = v.y;
                aggT[(r + 2) * PT + n] = v.z;
                aggT[(r + 3) * PT + n] = v.w;
            }
        }
    }
    // no barrier needed: gemm_T's internal chunk-0 barrier (wait+sync) orders
    // these STS before any C2 LDS (BAR.SYNC drains pending STS).

    // ---------------- Phase C2: acc += cur @ W2[0:128] ----------------------
    gemm_T(aggT, W2g, Ws, wsa, DD / CH, acc, lane, cw, tid, false);

    #pragma unroll
    for (int half = 0; half < 2; half++) {
        int n = base + lane + half * 32;
        if (n < N) {
            float o[16];
            #pragma unroll
            for (int j = 0; j < 8; j++) {
                float2 v = unpk(acc[half][j]);
                o[2*j]     = v.x + b2g[cw + 2*j];
                o[2*j + 1] = v.y + b2g[cw + 2*j + 1];
            }
            float* dp = dst + (size_t)n * DD + cw;
            #pragma unroll
            for (int q = 0; q < 4; q++)
                *(float4*)(dp + 4 * q) = *(float4*)&o[4 * q];
        }
    }
}

extern "C" void kernel_launch(void* const* d_in, const int* in_sizes, int n_in,
                              void* d_out, int out_size)
{
    const float* features = (const float*)d_in[0];
    const float* edge     = (const float*)d_in[1];
    const float* timef    = (const float*)d_in[2];
    const float* W1       = (const float*)d_in[3];
    const float* b1       = (const float*)d_in[4];
    const float* W2       = (const float*)d_in[5];
    const float* b2       = (const float*)d_in[6];
    const void*  idx      = d_in[7];
    float*       out      = (float*)d_out;

    const int N = in_sizes[0] / DD;

    const size_t smem = (size_t)(D1 * PT + 2 * CH * DD) * sizeof(float); // 66304 B
    cudaFuncSetAttribute(tgn_layer, cudaFuncAttributeMaxDynamicSharedMemorySize, (int)smem);

    void* gptr = nullptr;
    cudaGetSymbolAddress(&gptr, g_buf);
    float* gbuf = (float*)gptr;

    const int blocks = (N + TB - 1) / TB;
    const size_t eoff = (size_t)N * KK * DE;
    const size_t toff = (size_t)N * KK * DT;

    tgn_layer<<<blocks, 256, smem>>>(features, edge, timef,
                                     W1, b1, W2, b2, idx, 0, gbuf, N);
    tgn_layer<<<blocks, 256, smem>>>(gbuf, edge + eoff, timef + toff,
                                     W1 + D1 * DD, b1 + DD,
                                     W2 + 2 * DD * DD, b2 + DD,
                                     idx, 1, out, N);
}

// round 11
// speedup vs baseline: 1.8225x; 1.5636x over previous
#include <cuda_runtime.h>
#include <cstdint>

// ---------------------------------------------------------------------------
// TGN layer-graph sum embedding, fused per layer. Round 11: TF32 tensor cores.
// R4/R7/R10 all converged to L1~73-75% with fma pinned at its FFMA2 floor ->
// the scalar GEMM is structurally L1-wavefront-bound (6 LDS per 16 FFMA2).
// Replace GEMM core with mma.sync.m16n8k8.tf32:
//  - A row-major agg[64][196] (196%32=4): phase-A stores = consecutive STS.128
//    (conflict-free), A-frag loads (4*gid+tig) hit all 32 banks
//  - W staged pitch 136 (136%32=8): B-frag loads (8*tig+gid) conflict-free
//  - warp tile 32x32 (2 m-tiles x 4 n-tiles): per k8 = 8 mma + 16 LDS.32
//    (was 128 FFMA2 + 48 LDS wavefronts) -> GEMM L1 /3, math issue /8
//  - cvt.rna.tf32 at operand load; fp32 accumulate; ~1e-4 total rel err
// Same double-buffered cp.async W pipeline, same phase flow as R10.
// ---------------------------------------------------------------------------

#define DD   128
#define KK   16
#define DE   32
#define DT   32
#define D1   192
#define TB   64
#define PA_  196           // A pitch (floats), 196 % 32 == 4
#define PW_  136           // staged-W pitch, 136 % 32 == 8
#define CH   16            // W chunk rows
#define NMAX 100000

__device__ float g_buf[(size_t)NMAX * DD];

__device__ __forceinline__ uint32_t f2tf(float x) {
    uint32_t r; asm("cvt.rna.tf32.f32 %0, %1;" : "=r"(r) : "f"(x)); return r;
}
__device__ __forceinline__ void mma_tf32(float d[4], const uint32_t a[4], const uint32_t b[2]) {
    asm volatile(
        "mma.sync.aligned.m16n8k8.row.col.f32.tf32.tf32.f32 "
        "{%0,%1,%2,%3}, {%4,%5,%6,%7}, {%8,%9}, {%0,%1,%2,%3};"
        : "+f"(d[0]), "+f"(d[1]), "+f"(d[2]), "+f"(d[3])
        : "r"(a[0]), "r"(a[1]), "r"(a[2]), "r"(a[3]), "r"(b[0]), "r"(b[1]));
}
__device__ __forceinline__ void cpa16(uint32_t dst, const void* src) {
    asm volatile("cp.async.cg.shared.global [%0], [%1], 16;" :: "r"(dst), "l"(src));
}
__device__ __forceinline__ void cp_commit() { asm volatile("cp.async.commit_group;"); }
__device__ __forceinline__ void cp_wait0()  { asm volatile("cp.async.wait_group 0;"); }

// stage W chunk (16 rows x 128 cols, global row-major) into Ws[buf] pitch PW_
__device__ __forceinline__ void issue_chunk(uint32_t wsa, int buf,
                                            const float* Wg, int chunk, int tid) {
    const float4* s = (const float4*)(Wg + (size_t)chunk * CH * DD);
    uint32_t d = wsa + (uint32_t)buf * (CH * PW_ * 4);
    {
        int f = tid;              // float4 index 0..511
        int r = f >> 5, c = f & 31;
        cpa16(d + (uint32_t)(r * PW_ + c * 4) * 4, s + f);
    }
    {
        int f = tid + 256;
        int r = f >> 5, c = f & 31;
        cpa16(d + (uint32_t)(r * PW_ + c * 4) * 4, s + f);
    }
    cp_commit();
}

// acc[2 m-tiles][4 n-tiles][4] += A(64 x nCh*16, smem pitch PA_) @ W(nCh*16 x 128)
// Warp (mh, nq) owns rows [32mh,32mh+32) x cols [32nq,32nq+32).
// If pre==true, chunk 0 already issued. No trailing barrier (caller syncs).
__device__ __forceinline__ void gemm_mma(
    const float* __restrict__ Ag,
    const float* __restrict__ Wg,
    const float* __restrict__ Ws, uint32_t wsa,
    int nCh, float acc[2][4][4],
    int mh, int nq, int gid, int tig, int tid, bool pre)
{
    if (!pre) issue_chunk(wsa, 0, Wg, 0, tid);
    for (int c = 0; c < nCh; c++) {
        cp_wait0();
        __syncthreads();          // chunk c visible; prior-buf reads done
        if (c + 1 < nCh) issue_chunk(wsa, (c + 1) & 1, Wg, c + 1, tid);

        const float* wbase = Ws + (c & 1) * (CH * PW_);
        #pragma unroll
        for (int k8 = 0; k8 < 2; k8++) {
            const float* ap0 = Ag + (32 * mh + gid) * PA_ + c * CH + k8 * 8 + tig;
            uint32_t af[2][4];
            #pragma unroll
            for (int mi = 0; mi < 2; mi++) {
                const float* ap = ap0 + mi * 16 * PA_;
                af[mi][0] = f2tf(ap[0]);
                af[mi][1] = f2tf(ap[8 * PA_]);
                af[mi][2] = f2tf(ap[4]);
                af[mi][3] = f2tf(ap[8 * PA_ + 4]);
            }
            const float* wp = wbase + (k8 * 8 + tig) * PW_ + 32 * nq + gid;
            uint32_t bf[4][2];
            #pragma unroll
            for (int ni = 0; ni < 4; ni++) {
                bf[ni][0] = f2tf(wp[8 * ni]);
                bf[ni][1] = f2tf(wp[4 * PW_ + 8 * ni]);
            }
            #pragma unroll
            for (int mi = 0; mi < 2; mi++)
                #pragma unroll
                for (int ni = 0; ni < 4; ni++)
                    mma_tf32(acc[mi][ni], af[mi], bf[ni]);
        }
    }
}

extern "C" __global__ void __launch_bounds__(256, 3)
tgn_layer(const float* __restrict__ src,
          const float* __restrict__ e,
          const float* __restrict__ t,
          const float* __restrict__ W1g,
          const float* __restrict__ b1g,
          const float* __restrict__ W2g,
          const float* __restrict__ b2g,
          const void* __restrict__ idxRaw,
          int layer,
          float* __restrict__ dst,
          int N)
{
    extern __shared__ float sm[];
    float* agg = sm;                  // [64][PA_] row-major; cols 0..127 reused
    float* Ws  = agg + TB * PA_;      // [2][CH*PW_] double buffer
    __shared__ int s_flag;

    const int tid  = threadIdx.x;
    const int lane = tid & 31;
    const int w    = tid >> 5;
    const int gid  = lane >> 2;       // 0..7
    const int tig  = lane & 3;        // 0..3
    const int mh   = w & 1;           // m-half (rows 32*mh..)
    const int nq   = w >> 1;          // n-quarter (cols 32*nq..)
    const int base = blockIdx.x * TB;
    const uint32_t wsa = (uint32_t)__cvta_generic_to_shared(Ws);

    // prefetch W1 chunk 0 under phase A
    issue_chunk(wsa, 0, W1g, 0, tid);

    // idx dtype detection (int64 values < 1e5 -> every odd 32-bit word == 0)
    if (tid == 0) s_flag = 0;
    __syncthreads();
    if (tid < 64) {
        int v = ((const int*)idxRaw)[2 * tid + 1];
        if (v != 0) atomicOr(&s_flag, 1);
    }
    __syncthreads();
    const int idx64 = (s_flag == 0);

    const long long* i64 = (const long long*)idxRaw + (size_t)layer * N * KK;
    const int*       i32 = (const int*)idxRaw       + (size_t)layer * N * KK;

    // ---------------- Phase A: aggregation -> row-major smem ----------------
    #pragma unroll 1
    for (int i = 0; i < 8; i++) {
        int ln = w * 8 + i;
        int n  = base + ln;
        if (n >= N) continue;
        float4 accA = {0.f,0.f,0.f,0.f}, accB = {0.f,0.f,0.f,0.f};
        float es = 0.f, ts = 0.f;

        #pragma unroll
        for (int jj = 0; jj < 4; jj++) {
            long long q0, q1, q2, q3;
            if (idx64) {
                const long long* p = i64 + (size_t)n * KK + jj * 4;
                q0 = p[0]; q1 = p[1]; q2 = p[2]; q3 = p[3];
            } else {
                int4 v = ((const int4*)(i32 + (size_t)n * KK))[jj];
                q0 = v.x; q1 = v.y; q2 = v.z; q3 = v.w;
            }
            float4 v0 = ((const float4*)(src + (size_t)q0 * DD))[lane];
            float4 v1 = ((const float4*)(src + (size_t)q1 * DD))[lane];
            float4 v2 = ((const float4*)(src + (size_t)q2 * DD))[lane];
            float4 v3 = ((const float4*)(src + (size_t)q3 * DD))[lane];
            accA.x += v0.x; accA.y += v0.y; accA.z += v0.z; accA.w += v0.w;
            accB.x += v1.x; accB.y += v1.y; accB.z += v1.z; accB.w += v1.w;
            accA.x += v2.x; accA.y += v2.y; accA.z += v2.z; accA.w += v2.w;
            accB.x += v3.x; accB.y += v3.y; accB.z += v3.z; accB.w += v3.w;
        }
        const float* ep = e + (size_t)n * (KK * DE);
        const float* tp = t + (size_t)n * (KK * DT);
        #pragma unroll
        for (int j = 0; j < KK; j++) {
            es += ep[j * DE + lane];
            ts += tp[j * DT + lane];
        }
        accA.x += accB.x; accA.y += accB.y; accA.z += accB.z; accA.w += accB.w;

        *(float4*)&agg[ln * PA_ + 4 * lane] = accA;   // conflict-free STS.128
        agg[ln * PA_ + DD + lane]      = es;
        agg[ln * PA_ + DD + DE + lane] = ts;
    }
    __syncthreads();

    // ---------------- Phase B: h = relu(agg @ W1 + b1) ----------------------
    float acc[2][4][4];
    #pragma unroll
    for (int mi = 0; mi < 2; mi++)
        #pragma unroll
        for (int ni = 0; ni < 4; ni++)
            #pragma unroll
            for (int q = 0; q < 4; q++) acc[mi][ni][q] = 0.f;

    gemm_mma(agg, W1g, Ws, wsa, D1 / CH, acc, mh, nq, gid, tig, tid, true);

    // h -> agg cols [0,128). Safe: GEMM1's last chunk reads cols 176..191
    // only; reads of cols 0..175 precede its in-gemm barrier (chunk lockstep).
    #pragma unroll
    for (int mi = 0; mi < 2; mi++)
        #pragma unroll
        for (int ni = 0; ni < 4; ni++) {
            int row = 32 * mh + 16 * mi + gid;
            int col = 32 * nq + 8 * ni + 2 * tig;
            float bv0 = b1g[col], bv1 = b1g[col + 1];
            float2 lo = { fmaxf(acc[mi][ni][0] + bv0, 0.f),
                          fmaxf(acc[mi][ni][1] + bv1, 0.f) };
            float2 hi = { fmaxf(acc[mi][ni][2] + bv0, 0.f),
                          fmaxf(acc[mi][ni][3] + bv1, 0.f) };
            *(float2*)&agg[row * PA_ + col]       = lo;
            *(float2*)&agg[(row + 8) * PA_ + col] = hi;
            #pragma unroll
            for (int q = 0; q < 4; q++) acc[mi][ni][q] = 0.f;
        }
    __syncthreads();   // all h visible before C1 reads

    // ---------------- Phase C1: acc += h @ W2[128:256] ----------------------
    gemm_mma(agg, W2g + DD * DD, Ws, wsa, DD / CH, acc, mh, nq, gid, tig, tid, false);
    __syncthreads();   // C1 reads of cols 0..127 done before reload overwrites

    // ---------------- reload own rows (L2-hot) into agg cols 0..127 ---------
    {
        const float4* cp4 = (const float4*)(src + (size_t)base * DD);
        #pragma unroll
        for (int i = 0; i < 8; i++) {
            int f  = tid + 256 * i;      // 0..2047
            int n  = f >> 5;             // node 0..63
            int k4 = f & 31;
            if (base + n < N)
                *(float4*)&agg[n * PA_ + 4 * k4] = cp4[f];
        }
    }
    // ordering to C2's LDS: C2's chunk-0 wait+__syncthreads (BAR drains STS)

    // ---------------- Phase C2: acc += cur @ W2[0:128] ----------------------
    gemm_mma(agg, W2g, Ws, wsa, DD / CH, acc, mh, nq, gid, tig, tid, false);

    #pragma unroll
    for (int mi = 0; mi < 2; mi++)
        #pragma unroll
        for (int ni = 0; ni < 4; ni++) {
            int row = 32 * mh + 16 * mi + gid;
            int col = 32 * nq + 8 * ni + 2 * tig;
            float bv0 = b2g[col], bv1 = b2g[col + 1];
            int n1 = base + row, n2 = base + row + 8;
            if (n1 < N) {
                float2 o = { acc[mi][ni][0] + bv0, acc[mi][ni][1] + bv1 };
                *(float2*)&dst[(size_t)n1 * DD + col] = o;
            }
            if (n2 < N) {
                float2 o = { acc[mi][ni][2] + bv0, acc[mi][ni][3] + bv1 };
                *(float2*)&dst[(size_t)n2 * DD + col] = o;
            }
        }
}

extern "C" void kernel_launch(void* const* d_in, const int* in_sizes, int n_in,
                              void* d_out, int out_size)
{
    const float* features = (const float*)d_in[0];
    const float* edge     = (const float*)d_in[1];
    const float* timef    = (const float*)d_in[2];
    const float* W1       = (const float*)d_in[3];
    const float* b1       = (const float*)d_in[4];
    const float* W2       = (const float*)d_in[5];
    const float* b2       = (const float*)d_in[6];
    const void*  idx      = d_in[7];
    float*       out      = (float*)d_out;

    const int N = in_sizes[0] / DD;

    const size_t smem = (size_t)(TB * PA_ + 2 * CH * PW_) * sizeof(float); // 67,584 B
    cudaFuncSetAttribute(tgn_layer, cudaFuncAttributeMaxDynamicSharedMemorySize, (int)smem);

    void* gptr = nullptr;
    cudaGetSymbolAddress(&gptr, g_buf);
    float* gbuf = (float*)gptr;

    const int blocks = (N + TB - 1) / TB;
    const size_t eoff = (size_t)N * KK * DE;
    const size_t toff = (size_t)N * KK * DT;

    tgn_layer<<<blocks, 256, smem>>>(features, edge, timef,
                                     W1, b1, W2, b2, idx, 0, gbuf, N);
    tgn_layer<<<blocks, 256, smem>>>(gbuf, edge + eoff, timef + toff,
                                     W1 + D1 * DD, b1 + DD,
                                     W2 + 2 * DD * DD, b2 + DD,
                                     idx, 1, out, N);
}